// round 9
// baseline (speedup 1.0000x reference)
#include <cuda_runtime.h>
#include <cuda_bf16.h>
#include <math.h>

#define NN 100000
#define EE 1600000
#define F  128
#define G  64
#define PER 1562            // NN / G (last graph gets remainder)
#define EMB 768             // NHID*6
#define PSPLIT 16           // pool parallel splits per graph

// ---------------- scratch (static device globals; no allocation) ----------------
// NOTE: these symbols are ONLY referenced inside device code. Passing them as
// host-side kernel arguments yields the host shadow address (silently readable
// on GB300 via ATS) — that was the R7 correctness bug.
__device__ float g_h[(size_t)NN * F];      // h' = (x@W) * dinv[row]
__device__ float g_out[(size_t)NN * F];    // aggregation accumulator
__device__ float g_deg[NN];                // degree, then dinv (rsqrt)
__device__ int   g_pooled_bits[G * F];     // float bits, values >= 0 so int-max == float-max
__device__ float g_news[G * F];
__device__ float g_zcat[G * 1024];
__device__ float g_z1[G * 512];
__device__ float g_z2[G * 256];
__device__ float g_z3[G * 128];

// ---------------- degree ----------------
__global__ void k_deg_init() {
    int i = blockIdx.x * blockDim.x + threadIdx.x;
    if (i < NN) g_deg[i] = 1.0f;           // self loop
}

__global__ void k_deg_edge(const int* __restrict__ dst) {
    int e = blockIdx.x * blockDim.x + threadIdx.x;
    if (e < EE) atomicAdd(&g_deg[dst[e]], 1.0f);
}

__global__ void k_dinv() {
    int i = blockIdx.x * blockDim.x + threadIdx.x;
    if (i < NN) g_deg[i] = rsqrtf(g_deg[i]);   // deg >= 1 always
}

// zero the pooled-max accumulator (0 bits == 0.0f, valid floor for relu'd values)
__global__ void k_pool_init() {
    int i = blockIdx.x * blockDim.x + threadIdx.x;
    if (i < G * F) g_pooled_bits[i] = 0;
}

// ---------------- h' = (x @ conv_w) * dinv ; also init out accumulator ----------------
// 64 rows per block, 256 threads: warp w owns rows [8w,8w+8), lane owns 4 cols.
__global__ void __launch_bounds__(256) k_mm(const float* __restrict__ x,
                                            const float* __restrict__ w) {
    __shared__ float As[64 * F];
    int block_row = blockIdx.x * 64;
    for (int idx = threadIdx.x; idx < 64 * F; idx += 256) {
        int r = idx >> 7, k = idx & 127;
        int row = block_row + r;
        As[idx] = (row < NN) ? x[(size_t)row * F + k] : 0.0f;
    }
    __syncthreads();

    int c  = (threadIdx.x & 31) * 4;   // column base (4 consecutive cols)
    int rw = (threadIdx.x >> 5) * 8;   // row base within block (8 rows)

    float acc[8][4];
#pragma unroll
    for (int i = 0; i < 8; i++)
#pragma unroll
        for (int j = 0; j < 4; j++) acc[i][j] = 0.0f;

#pragma unroll 4
    for (int k = 0; k < F; k++) {
        float4 b4 = *reinterpret_cast<const float4*>(&w[k * F + c]);
#pragma unroll
        for (int i = 0; i < 8; i++) {
            float a = As[(rw + i) * F + k];   // broadcast LDS
            acc[i][0] += a * b4.x;
            acc[i][1] += a * b4.y;
            acc[i][2] += a * b4.z;
            acc[i][3] += a * b4.w;
        }
    }

#pragma unroll
    for (int i = 0; i < 8; i++) {
        int row = block_row + rw + i;
        if (row < NN) {
            float d = g_deg[row];
            float4 v = make_float4(acc[i][0] * d, acc[i][1] * d,
                                   acc[i][2] * d, acc[i][3] * d);
            *reinterpret_cast<float4*>(&g_h[(size_t)row * F + c])   = v;  // h'
            *reinterpret_cast<float4*>(&g_out[(size_t)row * F + c]) = v;  // self-loop init
        }
    }
}

// ---------------- edge scatter: out[dst] += h'[src]  (one warp per edge) ----------------
__global__ void __launch_bounds__(256) k_scatter(const int* __restrict__ src,
                                                 const int* __restrict__ dst) {
    int gt = blockIdx.x * blockDim.x + threadIdx.x;
    int e = gt >> 5;
    if (e >= EE) return;
    int lane = gt & 31;
    int s = __ldg(&src[e]);
    int d = __ldg(&dst[e]);
    float4 v = *reinterpret_cast<const float4*>(&g_h[(size_t)s * F + lane * 4]);
    float* p = &g_out[(size_t)d * F + lane * 4];
    asm volatile("red.global.add.v4.f32 [%0], {%1,%2,%3,%4};"
                 :: "l"(p), "f"(v.x), "f"(v.y), "f"(v.z), "f"(v.w)
                 : "memory");
}

// ---------------- pool: relu(dinv[i]*out[i] + b) then segment max ----------------
// grid (G, PSPLIT) x 128: block-local max over a slice, then int-bit atomicMax
// (valid: operands are >= 0 after relu, where int ordering == float ordering).
__global__ void k_pool(const float* __restrict__ conv_b) {
    int g = blockIdx.x, part = blockIdx.y, t = threadIdx.x;
    int seg_start = g * PER;
    int seg_end   = (g == G - 1) ? NN : seg_start + PER;
    int len   = seg_end - seg_start;
    int chunk = (len + PSPLIT - 1) / PSPLIT;
    int s = seg_start + part * chunk;
    int e = min(s + chunk, seg_end);
    float bb = conv_b[t];
    float m = 0.0f;                        // relu floor
    for (int i = s; i < e; i++) {
        float v = g_out[(size_t)i * F + t] * g_deg[i] + bb;
        m = fmaxf(m, v);                   // relu folded into floor==0
    }
    atomicMax(&g_pooled_bits[g * F + t], __float_as_int(m));
}

// ---------------- news = relu(x[first_idx] @ lin0_w + b0)  <<<G,128>>> ----------------
__global__ void k_news(const float* __restrict__ x,
                       const float* __restrict__ w,
                       const float* __restrict__ b) {
    int g = blockIdx.x, t = threadIdx.x;
    __shared__ float xs[F];
    xs[t] = x[(size_t)g * PER * F + t];    // first node of graph g = g*PER
    __syncthreads();
    float acc = b[t];
#pragma unroll 4
    for (int k = 0; k < F; k++) acc += xs[k] * w[k * F + t];
    g_news[g * F + t] = fmaxf(acc, 0.0f);
}

// ---------------- concat [pooled | news | emb]  <<<G,256>>> ----------------
__global__ void k_concat(const float* __restrict__ emb) {
    int g = blockIdx.x;
    for (int j = threadIdx.x; j < 1024; j += 256) {
        float v;
        if (j < 128)       v = __int_as_float(g_pooled_bits[g * F + j]);
        else if (j < 256)  v = g_news[g * F + (j - 128)];
        else               v = emb[g * EMB + (j - 256)];
        g_zcat[g * 1024 + j] = v;
    }
}

// ---------------- dense layer with tanh  grid(G, FO/128) x 128 ----------------
// LAYER selects in/out buffers *inside device code* so we never form a
// __device__-symbol address on the host (the R7 bug).
template <int FI, int FO, int LAYER>
__global__ void k_lin_tanh(const float* __restrict__ w,
                           const float* __restrict__ b) {
    const float* in  = (LAYER == 1) ? g_zcat : (LAYER == 2) ? g_z1 : g_z2;
    float*       out = (LAYER == 1) ? g_z1   : (LAYER == 2) ? g_z2 : g_z3;
    __shared__ float zs[FI];
    int g = blockIdx.x;
    for (int i = threadIdx.x; i < FI; i += 128) zs[i] = in[g * FI + i];
    __syncthreads();
    int c = blockIdx.y * 128 + threadIdx.x;
    if (c < FO) {
        float acc = b[c];
#pragma unroll 4
        for (int k = 0; k < FI; k++) acc += zs[k] * w[k * FO + c];
        out[g * FO + c] = tanhf(acc);
    }
}

// ---------------- final: logits + log_softmax  <<<1,G>>> ----------------
__global__ void k_head(const float* __restrict__ w,
                       const float* __restrict__ b,
                       float* __restrict__ out) {
    int g = threadIdx.x;
    float l0 = b[0], l1 = b[1];
#pragma unroll 4
    for (int k = 0; k < 128; k++) {
        float z = g_z3[g * 128 + k];
        l0 += z * w[k * 2 + 0];
        l1 += z * w[k * 2 + 1];
    }
    float m = fmaxf(l0, l1);
    float lse = m + logf(expf(l0 - m) + expf(l1 - m));
    out[g * 2 + 0] = l0 - lse;
    out[g * 2 + 1] = l1 - lse;
}

// ---------------- launch ----------------
extern "C" void kernel_launch(void* const* d_in, const int* in_sizes, int n_in,
                              void* d_out, int out_size) {
    const float* x      = (const float*)d_in[0];
    const float* emb    = (const float*)d_in[1];
    const float* conv_w = (const float*)d_in[2];
    const float* conv_b = (const float*)d_in[3];
    const float* lin0_w = (const float*)d_in[4];
    const float* lin0_b = (const float*)d_in[5];
    const float* lin1_w = (const float*)d_in[6];
    const float* lin1_b = (const float*)d_in[7];
    const float* lin2_w = (const float*)d_in[8];
    const float* lin2_b = (const float*)d_in[9];
    const float* lin3_w = (const float*)d_in[10];
    const float* lin3_b = (const float*)d_in[11];
    const float* lin4_w = (const float*)d_in[12];
    const float* lin4_b = (const float*)d_in[13];
    const int*   ei     = (const int*)d_in[14];   // [2, EE]: row0 = src, row1 = dst
    float* out = (float*)d_out;

    const int* src = ei;
    const int* dst = ei + EE;

    // degree -> dinv (pool-max init rides along, independent)
    k_deg_init<<<(NN + 255) / 256, 256>>>();
    k_pool_init<<<(G * F + 255) / 256, 256>>>();
    k_deg_edge<<<(EE + 255) / 256, 256>>>(dst);
    k_dinv<<<(NN + 255) / 256, 256>>>();

    // h' = (x@W)*dinv, out := h' (self loop)
    k_mm<<<(NN + 63) / 64, 256>>>(x, conv_w);

    // edge scatter-add (1 warp / edge)
    {
        long long threads = (long long)EE * 32;
        int blocks = (int)((threads + 255) / 256);
        k_scatter<<<blocks, 256>>>(src, dst);
    }

    // bias + relu + segment max (split 16-way per graph)
    k_pool<<<dim3(G, PSPLIT), 128>>>(conv_b);

    // news branch
    k_news<<<G, 128>>>(x, lin0_w, lin0_b);

    // concat + MLP head (buffers resolved on-device)
    k_concat<<<G, 256>>>(emb);
    k_lin_tanh<1024, 512, 1><<<dim3(G, 4), 128>>>(lin1_w, lin1_b);
    k_lin_tanh<512,  256, 2><<<dim3(G, 2), 128>>>(lin2_w, lin2_b);
    k_lin_tanh<256,  128, 3><<<dim3(G, 1), 128>>>(lin3_w, lin3_b);
    k_head<<<1, G>>>(lin4_w, lin4_b, out);
}

// round 13
// speedup vs baseline: 1.1090x; 1.1090x over previous
#include <cuda_runtime.h>
#include <cuda_bf16.h>
#include <math.h>

#define NN 100000
#define EE 1600000
#define F  128
#define G  64
#define PER 1562            // NN / G (last graph absorbs remainder)
#define EMB 768             // NHID*6
#define SCAN_CHUNK 1024     // elems per scan block (256 thr x 4)
#define SCAN_BLKS  98       // ceil(NN / 1024)

typedef unsigned long long ull;

// ---------------- scratch (device globals; only referenced in device code) ----------------
__device__ float g_h[(size_t)NN * F];      // h' = (x@W) * dinv[row]
__device__ int   g_cnt[NN];                // in-degree (edges only)
__device__ float g_deg[NN];                // dinv = rsqrt(cnt+1)
__device__ int   g_off[NN + 1];            // CSR offsets (by dst)
__device__ int   g_cur[NN];                // fill cursors
__device__ int   g_esrc[EE];               // CSR: src per slot
__device__ int   g_bsum[SCAN_BLKS];        // scan partials
__device__ int   g_pooled_bits[G * F];     // float bits; >=0 so int-max == float-max
__device__ float g_news[G * F];
__device__ float g_zcat[G * 1024];
__device__ float g_z1[G * 512];
__device__ float g_z2[G * 256];
__device__ float g_z3[G * 128];

// ---------------- f32x2 helpers (sm_103a packed fp32) ----------------
__device__ __forceinline__ void ffma2(ull& d, ull a, ull b) {
    asm("fma.rn.f32x2 %0, %1, %2, %0;" : "+l"(d) : "l"(a), "l"(b));
}
__device__ __forceinline__ ull splat2(float a) {
    ull r;
    asm("mov.b64 %0, {%1, %1};" : "=l"(r) : "r"(__float_as_uint(a)));
    return r;
}

// ---------------- degree ----------------
__global__ void k_deg_init() {
    int i = blockIdx.x * blockDim.x + threadIdx.x;
    if (i < NN) g_cnt[i] = 0;
}
__global__ void k_deg_edge(const int* __restrict__ dst) {
    int e = blockIdx.x * blockDim.x + threadIdx.x;
    if (e < EE) atomicAdd(&g_cnt[dst[e]], 1);
}
__global__ void k_dinv() {
    int i = blockIdx.x * blockDim.x + threadIdx.x;
    if (i < NN) g_deg[i] = rsqrtf((float)g_cnt[i] + 1.0f);   // +1 self loop
}

// ---------------- exclusive scan of g_cnt -> g_off ----------------
__global__ void k_scan1() {
    __shared__ int ssum[256];
    int t = threadIdx.x;
    int base = blockIdx.x * SCAN_CHUNK + t * 4;
    int c[4];
#pragma unroll
    for (int j = 0; j < 4; j++) {
        int i = base + j;
        c[j] = (i < NN) ? g_cnt[i] : 0;
    }
    int s = c[0] + c[1] + c[2] + c[3];
    ssum[t] = s;
    __syncthreads();
    // Hillis-Steele inclusive scan
    for (int off = 1; off < 256; off <<= 1) {
        int v = (t >= off) ? ssum[t - off] : 0;
        __syncthreads();
        ssum[t] += v;
        __syncthreads();
    }
    if (t == 255) g_bsum[blockIdx.x] = ssum[255];
    int run = ssum[t] - s;     // exclusive
#pragma unroll
    for (int j = 0; j < 4; j++) {
        int i = base + j;
        if (i < NN) g_off[i] = run;
        run += c[j];
    }
}
__global__ void k_scan2() {           // <<<1,1>>>: scan 98 partials
    int run = 0;
    for (int b = 0; b < SCAN_BLKS; b++) {
        int v = g_bsum[b];
        g_bsum[b] = run;
        run += v;
    }
    g_off[NN] = run;                  // == EE
}
__global__ void k_scan3() {
    int i = blockIdx.x * blockDim.x + threadIdx.x;
    if (i < NN) {
        int o = g_off[i] + g_bsum[i >> 10];
        g_off[i] = o;
        g_cur[i] = o;
    }
}

// ---------------- CSR fill: slot per edge (order nondeterministic; sum tolerant) ----------------
__global__ void k_fill(const int* __restrict__ src, const int* __restrict__ dst) {
    int e = blockIdx.x * blockDim.x + threadIdx.x;
    if (e < EE) {
        int pos = atomicAdd(&g_cur[dst[e]], 1);
        g_esrc[pos] = src[e];
    }
}

// zero pooled-max accumulator (0 bits == 0.0f == relu floor)
__global__ void k_pool_init() {
    int i = blockIdx.x * blockDim.x + threadIdx.x;
    if (i < G * F) g_pooled_bits[i] = 0;
}

// ---------------- h' = (x @ conv_w) * dinv  (f32x2 packed FMA) ----------------
// 64 rows/block, 256 threads. Thread: 4 rows x 8 cols (4 f32x2 pairs per row).
__global__ void __launch_bounds__(256) k_mm(const float* __restrict__ x,
                                            const float* __restrict__ w) {
    __shared__ float As[64 * 130];         // stride 130: conflict-free row-major reads
    int block_row = blockIdx.x * 64;
    for (int idx = threadIdx.x; idx < 64 * 128; idx += 256) {
        int r = idx >> 7, k = idx & 127;
        int row = block_row + r;
        As[r * 130 + k] = (row < NN) ? x[(size_t)row * F + k] : 0.0f;
    }
    __syncthreads();

    int cb = (threadIdx.x & 15) * 8;       // 8 consecutive cols
    int rg = (threadIdx.x >> 4) * 4;       // 4 consecutive rows

    ull acc[4][4];
#pragma unroll
    for (int i = 0; i < 4; i++)
#pragma unroll
        for (int p = 0; p < 4; p++) acc[i][p] = 0ull;   // (0.f,0.f)

#pragma unroll 4
    for (int k = 0; k < F; k++) {
        // 8 cols of w as 4 packed f32x2 (LDG.128 register pairs; no pack instrs)
        ulonglong2 bv0 = *reinterpret_cast<const ulonglong2*>(&w[k * F + cb]);
        ulonglong2 bv1 = *reinterpret_cast<const ulonglong2*>(&w[k * F + cb + 4]);
#pragma unroll
        for (int i = 0; i < 4; i++) {
            ull av = splat2(As[(rg + i) * 130 + k]);
            ffma2(acc[i][0], av, bv0.x);
            ffma2(acc[i][1], av, bv0.y);
            ffma2(acc[i][2], av, bv1.x);
            ffma2(acc[i][3], av, bv1.y);
        }
    }

#pragma unroll
    for (int i = 0; i < 4; i++) {
        int row = block_row + rg + i;
        if (row < NN) {
            float d = g_deg[row];
            float f[8];
#pragma unroll
            for (int p = 0; p < 4; p++) {
                f[2 * p]     = __uint_as_float((unsigned)(acc[i][p] & 0xffffffffull)) * d;
                f[2 * p + 1] = __uint_as_float((unsigned)(acc[i][p] >> 32)) * d;
            }
            *reinterpret_cast<float4*>(&g_h[(size_t)row * F + cb]) =
                make_float4(f[0], f[1], f[2], f[3]);
            *reinterpret_cast<float4*>(&g_h[(size_t)row * F + cb + 4]) =
                make_float4(f[4], f[5], f[6], f[7]);
        }
    }
}

// ---------------- fused pull-gather + bias + relu + segment-max ----------------
// Warp per node (8 nodes/warp serial), lane owns 4 cols. No float adds via atomics.
__device__ __forceinline__ void pool_flush(const float4& vmax, int g, int c) {
    atomicMax(&g_pooled_bits[g * F + c + 0], __float_as_int(vmax.x));
    atomicMax(&g_pooled_bits[g * F + c + 1], __float_as_int(vmax.y));
    atomicMax(&g_pooled_bits[g * F + c + 2], __float_as_int(vmax.z));
    atomicMax(&g_pooled_bits[g * F + c + 3], __float_as_int(vmax.w));
}

__global__ void __launch_bounds__(256) k_gather(const float* __restrict__ conv_b) {
    int warp  = (blockIdx.x * 256 + threadIdx.x) >> 5;
    int lane  = threadIdx.x & 31;
    int node0 = warp * 8;
    if (node0 >= NN) return;
    int c = lane * 4;
    float4 bb = *reinterpret_cast<const float4*>(&conv_b[c]);

    float4 vmax = make_float4(0.f, 0.f, 0.f, 0.f);
    int cur_g = min(node0 / PER, G - 1);

    for (int n = 0; n < 8; n++) {
        int d = node0 + n;
        if (d >= NN) break;
        int ng = d / PER;
        if (ng > G - 1) ng = G - 1;
        if (ng != cur_g) {
            pool_flush(vmax, cur_g, c);
            vmax = make_float4(0.f, 0.f, 0.f, 0.f);
            cur_g = ng;
        }
        // self loop term
        float4 sa = *reinterpret_cast<const float4*>(&g_h[(size_t)d * F + c]);
        float4 sb = make_float4(0.f, 0.f, 0.f, 0.f);
        int beg = g_off[d], end = g_off[d + 1];
        int j = beg;
        for (; j + 1 < end; j += 2) {          // dual accumulators: MLP=2
            int s0 = g_esrc[j], s1 = g_esrc[j + 1];
            float4 h0 = *reinterpret_cast<const float4*>(&g_h[(size_t)s0 * F + c]);
            float4 h1 = *reinterpret_cast<const float4*>(&g_h[(size_t)s1 * F + c]);
            sa.x += h0.x; sa.y += h0.y; sa.z += h0.z; sa.w += h0.w;
            sb.x += h1.x; sb.y += h1.y; sb.z += h1.z; sb.w += h1.w;
        }
        if (j < end) {
            int s0 = g_esrc[j];
            float4 h0 = *reinterpret_cast<const float4*>(&g_h[(size_t)s0 * F + c]);
            sa.x += h0.x; sa.y += h0.y; sa.z += h0.z; sa.w += h0.w;
        }
        float dv = g_deg[d];
        float vx = fmaxf((sa.x + sb.x) * dv + bb.x, 0.f);
        float vy = fmaxf((sa.y + sb.y) * dv + bb.y, 0.f);
        float vz = fmaxf((sa.z + sb.z) * dv + bb.z, 0.f);
        float vw = fmaxf((sa.w + sb.w) * dv + bb.w, 0.f);
        vmax.x = fmaxf(vmax.x, vx);
        vmax.y = fmaxf(vmax.y, vy);
        vmax.z = fmaxf(vmax.z, vz);
        vmax.w = fmaxf(vmax.w, vw);
    }
    pool_flush(vmax, cur_g, c);
}

// ---------------- news = relu(x[first_idx] @ lin0_w + b0)  <<<G,128>>> ----------------
__global__ void k_news(const float* __restrict__ x,
                       const float* __restrict__ w,
                       const float* __restrict__ b) {
    int g = blockIdx.x, t = threadIdx.x;
    __shared__ float xs[F];
    xs[t] = x[(size_t)g * PER * F + t];    // first node of graph g = g*PER
    __syncthreads();
    float acc = b[t];
#pragma unroll 4
    for (int k = 0; k < F; k++) acc += xs[k] * w[k * F + t];
    g_news[g * F + t] = fmaxf(acc, 0.0f);
}

// ---------------- concat [pooled | news | emb]  <<<G,256>>> ----------------
__global__ void k_concat(const float* __restrict__ emb) {
    int g = blockIdx.x;
    for (int j = threadIdx.x; j < 1024; j += 256) {
        float v;
        if (j < 128)       v = __int_as_float(g_pooled_bits[g * F + j]);
        else if (j < 256)  v = g_news[g * F + (j - 128)];
        else               v = emb[g * EMB + (j - 256)];
        g_zcat[g * 1024 + j] = v;
    }
}

// ---------------- dense layer with tanh; buffers resolved ON-DEVICE (R7 lesson) ----------------
template <int FI, int FO, int LAYER>
__global__ void k_lin_tanh(const float* __restrict__ w,
                           const float* __restrict__ b) {
    const float* in  = (LAYER == 1) ? g_zcat : (LAYER == 2) ? g_z1 : g_z2;
    float*       out = (LAYER == 1) ? g_z1   : (LAYER == 2) ? g_z2 : g_z3;
    __shared__ float zs[FI];
    int g = blockIdx.x;
    for (int i = threadIdx.x; i < FI; i += 128) zs[i] = in[g * FI + i];
    __syncthreads();
    int c = blockIdx.y * 128 + threadIdx.x;
    if (c < FO) {
        float acc = b[c];
#pragma unroll 4
        for (int k = 0; k < FI; k++) acc += zs[k] * w[k * FO + c];
        out[g * FO + c] = tanhf(acc);
    }
}

// ---------------- final: logits + log_softmax  <<<1,G>>> ----------------
__global__ void k_head(const float* __restrict__ w,
                       const float* __restrict__ b,
                       float* __restrict__ out) {
    int g = threadIdx.x;
    float l0 = b[0], l1 = b[1];
#pragma unroll 4
    for (int k = 0; k < 128; k++) {
        float z = g_z3[g * 128 + k];
        l0 += z * w[k * 2 + 0];
        l1 += z * w[k * 2 + 1];
    }
    float m = fmaxf(l0, l1);
    float lse = m + logf(expf(l0 - m) + expf(l1 - m));
    out[g * 2 + 0] = l0 - lse;
    out[g * 2 + 1] = l1 - lse;
}

// ---------------- launch ----------------
extern "C" void kernel_launch(void* const* d_in, const int* in_sizes, int n_in,
                              void* d_out, int out_size) {
    const float* x      = (const float*)d_in[0];
    const float* emb    = (const float*)d_in[1];
    const float* conv_w = (const float*)d_in[2];
    const float* conv_b = (const float*)d_in[3];
    const float* lin0_w = (const float*)d_in[4];
    const float* lin0_b = (const float*)d_in[5];
    const float* lin1_w = (const float*)d_in[6];
    const float* lin1_b = (const float*)d_in[7];
    const float* lin2_w = (const float*)d_in[8];
    const float* lin2_b = (const float*)d_in[9];
    const float* lin3_w = (const float*)d_in[10];
    const float* lin3_b = (const float*)d_in[11];
    const float* lin4_w = (const float*)d_in[12];
    const float* lin4_b = (const float*)d_in[13];
    const int*   ei     = (const int*)d_in[14];   // [2, EE]: row0 = src, row1 = dst
    float* out = (float*)d_out;

    const int* src = ei;
    const int* dst = ei + EE;

    // 1-5: degree + scan prologue (launch order keeps ncu -s 5 landing on k_mm)
    k_deg_init<<<(NN + 255) / 256, 256>>>();
    k_deg_edge<<<(EE + 255) / 256, 256>>>(dst);
    k_dinv<<<(NN + 255) / 256, 256>>>();
    k_scan1<<<SCAN_BLKS, 256>>>();
    k_scan2<<<1, 1>>>();

    // 6: h' = (x@W)*dinv  (f32x2 GEMM) — the profiled launch
    k_mm<<<(NN + 63) / 64, 256>>>(x, conv_w);

    // CSR finalize + fill
    k_scan3<<<(NN + 255) / 256, 256>>>();
    k_fill<<<(EE + 255) / 256, 256>>>(src, dst);

    // fused gather + bias + relu + segment-max
    k_pool_init<<<(G * F + 255) / 256, 256>>>();
    {
        int warps  = (NN + 7) / 8;
        int blocks = (warps * 32 + 255) / 256;
        k_gather<<<blocks, 256>>>(conv_b);
    }

    // news branch + MLP head
    k_news<<<G, 128>>>(x, lin0_w, lin0_b);
    k_concat<<<G, 256>>>(emb);
    k_lin_tanh<1024, 512, 1><<<dim3(G, 4), 128>>>(lin1_w, lin1_b);
    k_lin_tanh<512,  256, 2><<<dim3(G, 2), 128>>>(lin2_w, lin2_b);
    k_lin_tanh<256,  128, 3><<<dim3(G, 1), 128>>>(lin3_w, lin3_b);
    k_head<<<1, G>>>(lin4_w, lin4_b, out);
}

// round 15
// speedup vs baseline: 1.3879x; 1.2515x over previous
#include <cuda_runtime.h>
#include <cuda_bf16.h>
#include <math.h>

#define NN 100000
#define EE 1600000
#define F  128
#define G  64
#define PER 1562            // NN / G (last graph absorbs remainder)
#define EMB 768             // NHID*6
#define SCAN_CHUNK 1024     // elems per scan block (256 thr x 4)
#define SCAN_BLKS  98       // ceil(NN / 1024)

typedef unsigned long long ull;

// ---------------- scratch (device globals; only referenced in device code) ----------------
__device__ float g_h[(size_t)NN * F];      // h' = (x@W) * dinv[row]
__device__ int   g_cnt[NN];                // in-degree (edges only)
__device__ float g_deg[NN];                // dinv = rsqrt(cnt+1)
__device__ int   g_off[NN + 1];            // CSR offsets (by dst)
__device__ int   g_rank[EE];               // edge's slot within its dst bucket
__device__ int   g_esrc[EE];               // CSR: src per slot
__device__ int   g_bsum[SCAN_BLKS];        // scan partials
__device__ int   g_pooled_bits[G * F];     // float bits; >=0 so int-max == float-max
__device__ float g_news[G * F];
__device__ float g_zcat[G * 1024];
__device__ float g_z1[G * 512];
__device__ float g_z2[G * 256];
__device__ float g_z3[G * 128];

// ---------------- f32x2 helpers (sm_103a packed fp32) ----------------
__device__ __forceinline__ void ffma2(ull& d, ull a, ull b) {
    asm("fma.rn.f32x2 %0, %1, %2, %0;" : "+l"(d) : "l"(a), "l"(b));
}
__device__ __forceinline__ ull splat2(float a) {
    ull r;
    asm("mov.b64 %0, {%1, %1};" : "=l"(r) : "r"(__float_as_uint(a)));
    return r;
}

// ---------------- degree (+ pooled-max init folded in) ----------------
__global__ void k_deg_init() {
    int i = blockIdx.x * blockDim.x + threadIdx.x;
    if (i < NN) g_cnt[i] = 0;
    if (i < G * F) g_pooled_bits[i] = 0;   // 0 bits == 0.0f == relu floor
}
// count in-degree AND record each edge's rank within its dst bucket
__global__ void k_deg_edge(const int* __restrict__ dst) {
    int e = blockIdx.x * blockDim.x + threadIdx.x;
    if (e < EE) g_rank[e] = atomicAdd(&g_cnt[dst[e]], 1);
}
__global__ void k_dinv() {
    int i = blockIdx.x * blockDim.x + threadIdx.x;
    if (i < NN) g_deg[i] = rsqrtf((float)g_cnt[i] + 1.0f);   // +1 self loop
}

// ---------------- h' = (x @ conv_w) * dinv  (f32x2 packed FMA) ----------------
// 64 rows/block, 256 threads. Thread: 4 rows x 8 cols (4 f32x2 pairs per row).
// Launched 4th so ncu (-s 5 -c 1, empirically launch #4) profiles it.
__global__ void __launch_bounds__(256) k_mm(const float* __restrict__ x,
                                            const float* __restrict__ w) {
    __shared__ float As[64 * 130];         // stride 130: conflict-free row-major reads
    int block_row = blockIdx.x * 64;
    for (int idx = threadIdx.x; idx < 64 * 128; idx += 256) {
        int r = idx >> 7, k = idx & 127;
        int row = block_row + r;
        As[r * 130 + k] = (row < NN) ? x[(size_t)row * F + k] : 0.0f;
    }
    __syncthreads();

    int cb = (threadIdx.x & 15) * 8;       // 8 consecutive cols
    int rg = (threadIdx.x >> 4) * 4;       // 4 consecutive rows

    ull acc[4][4];
#pragma unroll
    for (int i = 0; i < 4; i++)
#pragma unroll
        for (int p = 0; p < 4; p++) acc[i][p] = 0ull;   // (0.f,0.f)

#pragma unroll 4
    for (int k = 0; k < F; k++) {
        ulonglong2 bv0 = *reinterpret_cast<const ulonglong2*>(&w[k * F + cb]);
        ulonglong2 bv1 = *reinterpret_cast<const ulonglong2*>(&w[k * F + cb + 4]);
#pragma unroll
        for (int i = 0; i < 4; i++) {
            ull av = splat2(As[(rg + i) * 130 + k]);
            ffma2(acc[i][0], av, bv0.x);
            ffma2(acc[i][1], av, bv0.y);
            ffma2(acc[i][2], av, bv1.x);
            ffma2(acc[i][3], av, bv1.y);
        }
    }

#pragma unroll
    for (int i = 0; i < 4; i++) {
        int row = block_row + rg + i;
        if (row < NN) {
            float d = g_deg[row];
            float f[8];
#pragma unroll
            for (int p = 0; p < 4; p++) {
                f[2 * p]     = __uint_as_float((unsigned)(acc[i][p] & 0xffffffffull)) * d;
                f[2 * p + 1] = __uint_as_float((unsigned)(acc[i][p] >> 32)) * d;
            }
            *reinterpret_cast<float4*>(&g_h[(size_t)row * F + cb]) =
                make_float4(f[0], f[1], f[2], f[3]);
            *reinterpret_cast<float4*>(&g_h[(size_t)row * F + cb + 4]) =
                make_float4(f[4], f[5], f[6], f[7]);
        }
    }
}

// ---------------- exclusive scan of g_cnt -> g_off ----------------
__global__ void k_scan1() {
    __shared__ int ssum[256];
    int t = threadIdx.x;
    int base = blockIdx.x * SCAN_CHUNK + t * 4;
    int c[4];
#pragma unroll
    for (int j = 0; j < 4; j++) {
        int i = base + j;
        c[j] = (i < NN) ? g_cnt[i] : 0;
    }
    int s = c[0] + c[1] + c[2] + c[3];
    ssum[t] = s;
    __syncthreads();
    for (int off = 1; off < 256; off <<= 1) {
        int v = (t >= off) ? ssum[t - off] : 0;
        __syncthreads();
        ssum[t] += v;
        __syncthreads();
    }
    if (t == 255) g_bsum[blockIdx.x] = ssum[255];
    int run = ssum[t] - s;     // exclusive
#pragma unroll
    for (int j = 0; j < 4; j++) {
        int i = base + j;
        if (i < NN) g_off[i] = run;
        run += c[j];
    }
}
__global__ void k_scan2() {           // <<<1,1>>>: scan 98 partials
    int run = 0;
    for (int b = 0; b < SCAN_BLKS; b++) {
        int v = g_bsum[b];
        g_bsum[b] = run;
        run += v;
    }
    g_off[NN] = run;                  // == EE
}
__global__ void k_scan3() {
    int i = blockIdx.x * blockDim.x + threadIdx.x;
    if (i < NN) g_off[i] = g_off[i] + g_bsum[i >> 10];
}

// ---------------- CSR fill: NO atomics (rank precomputed in deg pass) ----------------
__global__ void k_fill(const int* __restrict__ src, const int* __restrict__ dst) {
    int e = blockIdx.x * blockDim.x + threadIdx.x;
    if (e < EE) g_esrc[g_off[dst[e]] + g_rank[e]] = src[e];
}

// ---------------- fused pull-gather + bias + relu + segment-max ----------------
// Warp per 4 nodes, lane owns 4 cols. 4-wide neighbor unroll: all 4 index loads
// issue before the 4 row loads -> MLP 4+ per warp, 25k warps.
__device__ __forceinline__ void pool_flush(const float4& vmax, int g, int c) {
    atomicMax(&g_pooled_bits[g * F + c + 0], __float_as_int(vmax.x));
    atomicMax(&g_pooled_bits[g * F + c + 1], __float_as_int(vmax.y));
    atomicMax(&g_pooled_bits[g * F + c + 2], __float_as_int(vmax.z));
    atomicMax(&g_pooled_bits[g * F + c + 3], __float_as_int(vmax.w));
}
__device__ __forceinline__ void acc4(float4& a, const float4& h) {
    a.x += h.x; a.y += h.y; a.z += h.z; a.w += h.w;
}

__global__ void __launch_bounds__(256) k_gather(const float* __restrict__ conv_b) {
    int warp  = (blockIdx.x * 256 + threadIdx.x) >> 5;
    int lane  = threadIdx.x & 31;
    int node0 = warp * 4;
    if (node0 >= NN) return;
    int c = lane * 4;
    float4 bb = *reinterpret_cast<const float4*>(&conv_b[c]);

    float4 vmax = make_float4(0.f, 0.f, 0.f, 0.f);
    int cur_g = min(node0 / PER, G - 1);

#pragma unroll
    for (int n = 0; n < 4; n++) {
        int d = node0 + n;
        if (d >= NN) break;
        int ng = min(d / PER, G - 1);
        if (ng != cur_g) {
            pool_flush(vmax, cur_g, c);
            vmax = make_float4(0.f, 0.f, 0.f, 0.f);
            cur_g = ng;
        }
        float4 s0 = *reinterpret_cast<const float4*>(&g_h[(size_t)d * F + c]); // self loop
        float4 s1 = make_float4(0.f, 0.f, 0.f, 0.f);
        float4 s2 = make_float4(0.f, 0.f, 0.f, 0.f);
        float4 s3 = make_float4(0.f, 0.f, 0.f, 0.f);
        int beg = g_off[d], end = g_off[d + 1];
        int j = beg;
        for (; j + 3 < end; j += 4) {
            int i0 = g_esrc[j], i1 = g_esrc[j + 1], i2 = g_esrc[j + 2], i3 = g_esrc[j + 3];
            float4 h0 = *reinterpret_cast<const float4*>(&g_h[(size_t)i0 * F + c]);
            float4 h1 = *reinterpret_cast<const float4*>(&g_h[(size_t)i1 * F + c]);
            float4 h2 = *reinterpret_cast<const float4*>(&g_h[(size_t)i2 * F + c]);
            float4 h3 = *reinterpret_cast<const float4*>(&g_h[(size_t)i3 * F + c]);
            acc4(s0, h0); acc4(s1, h1); acc4(s2, h2); acc4(s3, h3);
        }
        for (; j < end; j++) {
            float4 h0 = *reinterpret_cast<const float4*>(&g_h[(size_t)g_esrc[j] * F + c]);
            acc4(s0, h0);
        }
        float dv = g_deg[d];
        float vx = fmaxf(((s0.x + s1.x) + (s2.x + s3.x)) * dv + bb.x, 0.f);
        float vy = fmaxf(((s0.y + s1.y) + (s2.y + s3.y)) * dv + bb.y, 0.f);
        float vz = fmaxf(((s0.z + s1.z) + (s2.z + s3.z)) * dv + bb.z, 0.f);
        float vw = fmaxf(((s0.w + s1.w) + (s2.w + s3.w)) * dv + bb.w, 0.f);
        vmax.x = fmaxf(vmax.x, vx);
        vmax.y = fmaxf(vmax.y, vy);
        vmax.z = fmaxf(vmax.z, vz);
        vmax.w = fmaxf(vmax.w, vw);
    }
    pool_flush(vmax, cur_g, c);
}

// ---------------- news = relu(x[first_idx] @ lin0_w + b0)  <<<G,128>>> ----------------
__global__ void k_news(const float* __restrict__ x,
                       const float* __restrict__ w,
                       const float* __restrict__ b) {
    int g = blockIdx.x, t = threadIdx.x;
    __shared__ float xs[F];
    xs[t] = x[(size_t)g * PER * F + t];    // first node of graph g = g*PER
    __syncthreads();
    float acc = b[t];
#pragma unroll 4
    for (int k = 0; k < F; k++) acc += xs[k] * w[k * F + t];
    g_news[g * F + t] = fmaxf(acc, 0.0f);
}

// ---------------- concat [pooled | news | emb]  <<<G,256>>> ----------------
__global__ void k_concat(const float* __restrict__ emb) {
    int g = blockIdx.x;
    for (int j = threadIdx.x; j < 1024; j += 256) {
        float v;
        if (j < 128)       v = __int_as_float(g_pooled_bits[g * F + j]);
        else if (j < 256)  v = g_news[g * F + (j - 128)];
        else               v = emb[g * EMB + (j - 256)];
        g_zcat[g * 1024 + j] = v;
    }
}

// ---------------- dense layer with tanh; smem-tiled weights ----------------
// grid(G, FO/128) x 128. Weight tile 64k x 128c staged in smem so the inner
// product runs on LDS (29 cyc, pipelined) instead of a serial L2-latency chain.
// Buffers resolved ON-DEVICE (R7 lesson).
template <int FI, int FO, int LAYER>
__global__ void __launch_bounds__(128) k_lin_tanh(const float* __restrict__ w,
                                                  const float* __restrict__ b) {
    const float* in  = (LAYER == 1) ? g_zcat : (LAYER == 2) ? g_z1 : g_z2;
    float*       out = (LAYER == 1) ? g_z1   : (LAYER == 2) ? g_z2 : g_z3;
    __shared__ float zs[FI];
    __shared__ float wt[64 * 128];         // 32 KB tile
    int g = blockIdx.x;
    int cb0 = blockIdx.y * 128;
    for (int i = threadIdx.x; i < FI; i += 128) zs[i] = in[g * FI + i];

    int c = cb0 + threadIdx.x;
    float acc = b[c];
    for (int t0 = 0; t0 < FI; t0 += 64) {
        __syncthreads();
        // cooperative tile load: rows [t0,t0+64) x cols [cb0,cb0+128), float4
        for (int idx = threadIdx.x; idx < 64 * 32; idx += 128) {
            int r = idx >> 5, q = idx & 31;
            *reinterpret_cast<float4*>(&wt[r * 128 + q * 4]) =
                *reinterpret_cast<const float4*>(&w[(size_t)(t0 + r) * FO + cb0 + q * 4]);
        }
        __syncthreads();
#pragma unroll 16
        for (int k = 0; k < 64; k++)
            acc += zs[t0 + k] * wt[k * 128 + threadIdx.x];
    }
    out[g * FO + c] = tanhf(acc);
}

// ---------------- final: logits + log_softmax  <<<1,G>>> ----------------
__global__ void k_head(const float* __restrict__ w,
                       const float* __restrict__ b,
                       float* __restrict__ out) {
    int g = threadIdx.x;
    float l0 = b[0], l1 = b[1];
#pragma unroll 4
    for (int k = 0; k < 128; k++) {
        float z = g_z3[g * 128 + k];
        l0 += z * w[k * 2 + 0];
        l1 += z * w[k * 2 + 1];
    }
    float m = fmaxf(l0, l1);
    float lse = m + logf(expf(l0 - m) + expf(l1 - m));
    out[g * 2 + 0] = l0 - lse;
    out[g * 2 + 1] = l1 - lse;
}

// ---------------- launch ----------------
extern "C" void kernel_launch(void* const* d_in, const int* in_sizes, int n_in,
                              void* d_out, int out_size) {
    const float* x      = (const float*)d_in[0];
    const float* emb    = (const float*)d_in[1];
    const float* conv_w = (const float*)d_in[2];
    const float* conv_b = (const float*)d_in[3];
    const float* lin0_w = (const float*)d_in[4];
    const float* lin0_b = (const float*)d_in[5];
    const float* lin1_w = (const float*)d_in[6];
    const float* lin1_b = (const float*)d_in[7];
    const float* lin2_w = (const float*)d_in[8];
    const float* lin2_b = (const float*)d_in[9];
    const float* lin3_w = (const float*)d_in[10];
    const float* lin3_b = (const float*)d_in[11];
    const float* lin4_w = (const float*)d_in[12];
    const float* lin4_b = (const float*)d_in[13];
    const int*   ei     = (const int*)d_in[14];   // [2, EE]: row0 = src, row1 = dst
    float* out = (float*)d_out;

    const int* src = ei;
    const int* dst = ei + EE;

    // 1-3: degree (+rank) -> dinv
    k_deg_init<<<(NN + 255) / 256, 256>>>();
    k_deg_edge<<<(EE + 255) / 256, 256>>>(dst);
    k_dinv<<<(NN + 255) / 256, 256>>>();

    // 4: h' = (x@W)*dinv — launch #4, the one ncu profiles
    k_mm<<<(NN + 63) / 64, 256>>>(x, conv_w);

    // CSR offsets + atomic-free fill
    k_scan1<<<SCAN_BLKS, 256>>>();
    k_scan2<<<1, 1>>>();
    k_scan3<<<(NN + 255) / 256, 256>>>();
    k_fill<<<(EE + 255) / 256, 256>>>(src, dst);

    // fused gather + bias + relu + segment-max (4 nodes/warp)
    {
        int warps  = (NN + 3) / 4;
        int blocks = (warps * 32 + 255) / 256;
        k_gather<<<blocks, 256>>>(conv_b);
    }

    // news branch + MLP head
    k_news<<<G, 128>>>(x, lin0_w, lin0_b);
    k_concat<<<G, 256>>>(emb);
    k_lin_tanh<1024, 512, 1><<<dim3(G, 4), 128>>>(lin1_w, lin1_b);
    k_lin_tanh<512,  256, 2><<<dim3(G, 2), 128>>>(lin2_w, lin2_b);
    k_lin_tanh<256,  128, 3><<<dim3(G, 1), 128>>>(lin3_w, lin3_b);
    k_head<<<1, G>>>(lin4_w, lin4_b, out);
}